// round 13
// baseline (speedup 1.0000x reference)
#include <cuda_runtime.h>
#include <cstdint>

#define NB 1024
#define ND 128
#define TI 64               // i-tile
#define TJ 32               // j-tile
#define NIB (NB / TI)       // 16
#define NJB (NB / TJ)       // 32
#define NCTA (NIB * NJB)    // 512
#define RSTRIDE 132         // padded floats per row (conflict-free LDS.32 / STS.128)

__device__ __align__(16) float g_part[NB * NJB];  // [i][jb]
__device__ float g_pos[NB];
__device__ unsigned int g_ctr = 0;

// ---- smem layout (bytes) ----
#define OFF_A    0                          // 64 x 132 f = 33792
#define OFF_B    33792                      // 32 x 132 f = 16896
#define OFF_N1   50688                      // 64 f
#define OFF_RN1  50944
#define OFF_N2   51200                      // 32 f
#define OFF_RN2  51328
#define OFF_PA   51456                      // ssq partials A [4][64] f
#define OFF_PB   52480                      // ssq partials B [8][32] f
#define OFF_RP   53504                      // rowpart [2][64] f
#define OFF_RED  54016                      // 8 f
#define OFF_FLAG 54048
#define SMEM_TOTAL 54272

__device__ __forceinline__ uint32_t cvt_tf32(float x) {
  uint32_t o;
  asm("cvt.rna.tf32.f32 %0, %1;" : "=r"(o) : "f"(x));
  return o;
}
__device__ __forceinline__ void mma_tf32(float* d, const uint32_t* a, uint32_t b0, uint32_t b1) {
  asm volatile(
      "mma.sync.aligned.m16n8k8.row.col.f32.tf32.tf32.f32 "
      "{%0,%1,%2,%3}, {%4,%5,%6,%7}, {%8,%9}, {%0,%1,%2,%3};"
      : "+f"(d[0]), "+f"(d[1]), "+f"(d[2]), "+f"(d[3])
      : "r"(a[0]), "r"(a[1]), "r"(a[2]), "r"(a[3]), "r"(b0), "r"(b1));
}

__global__ __launch_bounds__(256, 4) void hyp_fused(const float* __restrict__ z1,
                                                    const float* __restrict__ z2,
                                                    float* __restrict__ out) {
  extern __shared__ char sm[];
  float* smf = reinterpret_cast<float*>(sm);
  float* sn1 = reinterpret_cast<float*>(sm + OFF_N1);
  float* srn1 = reinterpret_cast<float*>(sm + OFF_RN1);
  float* sn2 = reinterpret_cast<float*>(sm + OFF_N2);
  float* srn2 = reinterpret_cast<float*>(sm + OFF_RN2);
  float* pA = reinterpret_cast<float*>(sm + OFF_PA);
  float* pB = reinterpret_cast<float*>(sm + OFF_PB);
  float* rowpart = reinterpret_cast<float*>(sm + OFF_RP);
  float* red = reinterpret_cast<float*>(sm + OFF_RED);
  int* flag = reinterpret_cast<int*>(sm + OFF_FLAG);

  const int tid = threadIdx.x;
  const int wid = tid >> 5;
  const int lane = tid & 31;
  const int g4 = lane >> 2;     // thread group (0..7)
  const int c0 = lane & 3;      // thread in group
  const int wi = wid & 3;       // warp i-position: 16 rows each
  const int wj = wid >> 2;      // warp j-position: 16 cols each
  const int jb = blockIdx.x;    // 0..31
  const int ib = blockIdx.y;    // 0..15
  const int i0 = ib * TI;
  const int j0 = jb * TJ;

  // ---- stage A: 64 rows; thread t -> row t&63, 128B chunk (t>>6) ----
  {
    const int r = tid & 63, cg = tid >> 6;
    const float* src = z1 + (size_t)(i0 + r) * ND + cg * 32;
    float ssq = 0.f;
    #pragma unroll
    for (int i = 0; i < 8; ++i) {
      float4 v = *reinterpret_cast<const float4*>(src + 4 * i);
      ssq += v.x * v.x + v.y * v.y + v.z * v.z + v.w * v.w;
      uint4 w = make_uint4(cvt_tf32(v.x), cvt_tf32(v.y), cvt_tf32(v.z), cvt_tf32(v.w));
      *reinterpret_cast<uint4*>(sm + OFF_A + (r * RSTRIDE + cg * 32 + 4 * i) * 4) = w;
    }
    pA[cg * 64 + r] = ssq;
  }
  // ---- stage B: 32 rows; thread t -> row t&31, 64B chunk (t>>5) ----
  {
    const int r = tid & 31, cg = tid >> 5;
    const float* src = z2 + (size_t)(j0 + r) * ND + cg * 16;
    float ssq = 0.f;
    #pragma unroll
    for (int i = 0; i < 4; ++i) {
      float4 v = *reinterpret_cast<const float4*>(src + 4 * i);
      ssq += v.x * v.x + v.y * v.y + v.z * v.z + v.w * v.w;
      uint4 w = make_uint4(cvt_tf32(v.x), cvt_tf32(v.y), cvt_tf32(v.z), cvt_tf32(v.w));
      *reinterpret_cast<uint4*>(sm + OFF_B + (r * RSTRIDE + cg * 16 + 4 * i) * 4) = w;
    }
    pB[cg * 32 + r] = ssq;
  }
  __syncthreads();
  // ---- finish norms (deterministic fixed-order sums) ----
  if (tid < 64) {
    float s = pA[tid] + pA[64 + tid] + pA[128 + tid] + pA[192 + tid];
    sn1[tid] = s;
    srn1[tid] = 1.0f / fmaxf(sqrtf(s), 1e-12f);
  } else if (tid < 96) {
    const int j = tid - 64;
    float s = 0.f;
    #pragma unroll
    for (int k = 0; k < 8; ++k) s += pB[k * 32 + j];
    sn2[j] = s;
    srn2[j] = 1.0f / fmaxf(sqrtf(s), 1e-12f);
  }
  __syncthreads();

  // ---- main loop: 16 k8 steps, all-immediate LDS.32, conflict-free ----
  const float* ap = reinterpret_cast<const float*>(sm + OFF_A) + (wi * 16 + g4) * RSTRIDE + c0;
  const float* bp = reinterpret_cast<const float*>(sm + OFF_B) + (wj * 16 + g4) * RSTRIDE + c0;
  float acc[2][4];
  #pragma unroll
  for (int t = 0; t < 2; ++t)
    #pragma unroll
    for (int e = 0; e < 4; ++e) acc[t][e] = 0.f;

  #pragma unroll
  for (int s = 0; s < 16; ++s) {
    uint32_t a[4], b00, b01, b10, b11;
    a[0] = __float_as_uint(ap[s * 8]);
    a[1] = __float_as_uint(ap[s * 8 + 8 * RSTRIDE]);
    a[2] = __float_as_uint(ap[s * 8 + 4]);
    a[3] = __float_as_uint(ap[s * 8 + 8 * RSTRIDE + 4]);
    b00 = __float_as_uint(bp[s * 8]);
    b01 = __float_as_uint(bp[s * 8 + 4]);
    b10 = __float_as_uint(bp[s * 8 + 8 * RSTRIDE]);
    b11 = __float_as_uint(bp[s * 8 + 8 * RSTRIDE + 4]);
    mma_tf32(acc[0], a, b00, b01);
    mma_tf32(acc[1], a, b10, b11);
  }

  // ---- epilogue: hyperbolic + cosine sim, exp, per-row sums ----
  const float CC = 0.05f, SQC = 0.22360679774997896f, KD = 22.360679774997896f;
  #pragma unroll
  for (int rh = 0; rh < 2; ++rh) {
    const int rowl = wi * 16 + g4 + 8 * rh;
    const int ig = i0 + rowl;
    const float n1 = sn1[rowl];
    const float rn1 = srn1[rowl];
    float rs = 0.f;
    #pragma unroll
    for (int t = 0; t < 2; ++t) {
      #pragma unroll
      for (int e = 0; e < 2; ++e) {
        const int col = wj * 16 + t * 8 + c0 * 2 + e;
        const float g = acc[t][rh * 2 + e];
        const float n2 = sn2[col];
        const float xy = -g;
        const float Af = fmaf(0.1f, xy, fmaf(CC, n2, 1.0f));
        const float Bf = 1.0f - CC * n1;
        const float den = fmaxf(fmaf(0.1f, xy, fmaf(CC * CC, n1 * n2, 1.0f)), 1e-6f);
        const float num2 = Af * Af * n1 + Bf * Bf * n2 + 2.0f * Af * Bf * xy;
        const float s = SQC * sqrtf(fmaxf(num2, 0.0f));
        float r = __fdividef(den + s, fmaxf(den - s, 1e-6f * den));
        r = fminf(r, 2.0e6f);
        const float sim = fmaf(5.0f * g, rn1 * srn2[col], -KD * __logf(r));
        if (ig == j0 + col) g_pos[ig] = sim;
        else rs += __expf(sim);
      }
    }
    rs += __shfl_xor_sync(0xffffffffu, rs, 1);
    rs += __shfl_xor_sync(0xffffffffu, rs, 2);
    if (c0 == 0) rowpart[wj * 64 + rowl] = rs;
  }
  __syncthreads();
  if (tid < TI) g_part[(i0 + tid) * NJB + jb] = rowpart[tid] + rowpart[64 + tid];

  // ---- last-CTA fused final reduction (deterministic order) ----
  __threadfence();
  __syncthreads();
  if (tid == 0) {
    unsigned t = atomicAdd(&g_ctr, 1u);
    *flag = (t == NCTA - 1) ? 1 : 0;
  }
  __syncthreads();
  if (*flag) {
    __threadfence();
    float acc2 = 0.f;
    #pragma unroll
    for (int q = 0; q < 4; ++q) {
      const int i = tid + q * 256;
      const float4* rp = reinterpret_cast<const float4*>(g_part + i * NJB);
      float ssum = 0.f;
      #pragma unroll
      for (int b = 0; b < NJB / 4; ++b) {
        float4 v = rp[b];
        ssum += v.x + v.y + v.z + v.w;
      }
      acc2 += __logf(ssum) - g_pos[i];
    }
    #pragma unroll
    for (int off = 16; off; off >>= 1) acc2 += __shfl_down_sync(0xffffffffu, acc2, off);
    if ((tid & 31) == 0) red[tid >> 5] = acc2;
    __syncthreads();
    if (tid == 0) {
      float tt = 0.f;
      #pragma unroll
      for (int w = 0; w < 8; ++w) tt += red[w];
      out[0] = tt * (1.0f / NB);
      g_ctr = 0;  // reset for next graph replay
    }
  }
}

extern "C" void kernel_launch(void* const* d_in, const int* in_sizes, int n_in,
                              void* d_out, int out_size) {
  const float* z1 = (const float*)d_in[0];
  const float* z2 = (const float*)d_in[1];
  (void)in_sizes; (void)n_in; (void)out_size;

  cudaFuncSetAttribute(hyp_fused, cudaFuncAttributeMaxDynamicSharedMemorySize, SMEM_TOTAL);

  dim3 grid(NJB, NIB);
  hyp_fused<<<grid, 256, SMEM_TOTAL>>>(z1, z2, (float*)d_out);
}

// round 15
// speedup vs baseline: 1.4228x; 1.4228x over previous
#include <cuda_runtime.h>
#include <cstdint>

#define NB 1024
#define ND 128
#define TT 64               // square tile
#define NBLK 16             // NB / TT
#define NCTA 256
#define ROWB 512            // 128 tf32 * 4B per row

__device__ __align__(16) float g_part[NB * NBLK];  // [i][jb], 64B per i-row
__device__ float g_pos[NB];
__device__ unsigned int g_ctr = 0;

// ---- smem layout (bytes) ----
#define OFF_A    0                    // 64 x 512 = 32768
#define OFF_B    32768                // 64 x 512 = 32768
#define OFF_N1   65536                // 64 f
#define OFF_RN1  65792
#define OFF_N2   66048
#define OFF_RN2  66304
#define OFF_PA   66560                // ssq partials [4][64] f
#define OFF_PB   67584                // ssq partials [4][64] f
#define OFF_RP   68608                // rowpart [2][64] f
#define OFF_RED  69120                // 8 f
#define OFF_FLAG 69152
#define SMEM_TOTAL 69376              // ~68 KB -> 2 CTAs/SM

__device__ __forceinline__ uint32_t smem_u32(const void* p) {
  uint32_t a;
  asm("{ .reg .u64 t; cvta.to.shared.u64 t, %1; cvt.u32.u64 %0, t; }" : "=r"(a) : "l"(p));
  return a;
}
__device__ __forceinline__ uint32_t cvt_tf32(float x) {
  uint32_t o;
  asm("cvt.rna.tf32.f32 %0, %1;" : "=r"(o) : "f"(x));
  return o;
}
#define LDSM_X4(r0, r1, r2, r3, addr) \
  asm volatile("ldmatrix.sync.aligned.m8n8.x4.shared.b16 {%0,%1,%2,%3}, [%4];" \
               : "=r"(r0), "=r"(r1), "=r"(r2), "=r"(r3) : "r"(addr))
__device__ __forceinline__ void mma_tf32(float* d, const uint32_t* a, uint32_t b0, uint32_t b1) {
  asm volatile(
      "mma.sync.aligned.m16n8k8.row.col.f32.tf32.tf32.f32 "
      "{%0,%1,%2,%3}, {%4,%5,%6,%7}, {%8,%9}, {%0,%1,%2,%3};"
      : "+f"(d[0]), "+f"(d[1]), "+f"(d[2]), "+f"(d[3])
      : "r"(a[0]), "r"(a[1]), "r"(a[2]), "r"(a[3]), "r"(b0), "r"(b1));
}

// Stage one 64x128 fp32 tile as tf32, XOR-swizzled 16B chunks + ssq partials.
__device__ __forceinline__ void stage_tile(const float* __restrict__ src, char* smtile,
                                           float* pssq, int tid) {
  const int r = tid & 63, cg = tid >> 6;           // row, 32-float chunk-group
  const float* row = src + (size_t)r * ND + cg * 32;
  char* rbase = smtile + r * ROWB;
  const int s = r & 7;
  float ssq = 0.f;
  #pragma unroll
  for (int i = 0; i < 8; ++i) {
    float4 v = *reinterpret_cast<const float4*>(row + 4 * i);
    ssq += v.x * v.x + v.y * v.y + v.z * v.z + v.w * v.w;
    uint4 w = make_uint4(cvt_tf32(v.x), cvt_tf32(v.y), cvt_tf32(v.z), cvt_tf32(v.w));
    *reinterpret_cast<uint4*>(rbase + ((cg * 8 + i) ^ s) * 16) = w;
  }
  pssq[cg * 64 + r] = ssq;
}

__global__ __launch_bounds__(256, 2) void hyp_fused(const float* __restrict__ z1,
                                                    const float* __restrict__ z2,
                                                    float* __restrict__ out) {
  extern __shared__ char sm[];
  const uint32_t smb = smem_u32(sm);
  float* sn1 = reinterpret_cast<float*>(sm + OFF_N1);
  float* srn1 = reinterpret_cast<float*>(sm + OFF_RN1);
  float* sn2 = reinterpret_cast<float*>(sm + OFF_N2);
  float* srn2 = reinterpret_cast<float*>(sm + OFF_RN2);
  float* pA = reinterpret_cast<float*>(sm + OFF_PA);
  float* pB = reinterpret_cast<float*>(sm + OFF_PB);
  float* rowpart = reinterpret_cast<float*>(sm + OFF_RP);
  float* red = reinterpret_cast<float*>(sm + OFF_RED);
  int* flag = reinterpret_cast<int*>(sm + OFF_FLAG);

  const int tid = threadIdx.x;
  const int wid = tid >> 5;
  const int lane = tid & 31;
  const int g4 = lane >> 2, c0 = lane & 3;
  const int wi = wid & 3;        // 4 warps x 16 rows
  const int wj = wid >> 2;       // 2 warps x 32 cols
  const int jb = blockIdx.x;
  const int ib = blockIdx.y;
  const int i0 = ib * TT;
  const int j0 = jb * TT;

  // ---- fused stage: fp32 -> tf32 + norms ----
  stage_tile(z1 + (size_t)i0 * ND, sm + OFF_A, pA, tid);
  stage_tile(z2 + (size_t)j0 * ND, sm + OFF_B, pB, tid);
  __syncthreads();
  if (tid < 64) {
    float s = pA[tid] + pA[64 + tid] + pA[128 + tid] + pA[192 + tid];
    sn1[tid] = s;
    srn1[tid] = 1.0f / fmaxf(sqrtf(s), 1e-12f);
  } else if (tid < 128) {
    const int j = tid - 64;
    float s = pB[j] + pB[64 + j] + pB[128 + j] + pB[192 + j];
    sn2[j] = s;
    srn2[j] = 1.0f / fmaxf(sqrtf(s), 1e-12f);
  }
  __syncthreads();

  // ---- ldmatrix addressing (tf32 fragments via b16 x4) ----
  const int arow = wi * 16 + (lane & 15);
  const uint32_t abase = smb + OFF_A + arow * ROWB;
  const uint32_t asx = (uint32_t)(arow & 7) << 4;
  const uint32_t ahalf = (uint32_t)(lane >> 4) << 4;     // k-half chunk bit, pre-shifted
  const int brow = wj * 32 + (lane & 7) + ((lane >> 4) << 3);
  const uint32_t bbase0 = smb + OFF_B + brow * ROWB;
  const uint32_t bbase1 = bbase0 + 16 * ROWB;
  const uint32_t bsx = (uint32_t)(brow & 7) << 4;
  const uint32_t bhalf = (uint32_t)((lane >> 3) & 1) << 4;

  float acc[4][4];
  #pragma unroll
  for (int n = 0; n < 4; ++n)
    #pragma unroll
    for (int e = 0; e < 4; ++e) acc[n][e] = 0.f;

  // ---- main loop: 16 k8 steps ----
  #pragma unroll
  for (int ks = 0; ks < 16; ++ks) {
    const uint32_t kc = (uint32_t)(ks * 2) << 4;
    uint32_t a[4], b[2][4];
    LDSM_X4(a[0], a[1], a[2], a[3], abase + ((kc + ahalf) ^ asx));
    LDSM_X4(b[0][0], b[0][1], b[0][2], b[0][3], bbase0 + ((kc + bhalf) ^ bsx));
    LDSM_X4(b[1][0], b[1][1], b[1][2], b[1][3], bbase1 + ((kc + bhalf) ^ bsx));
    mma_tf32(acc[0], a, b[0][0], b[0][1]);   // n-octet 0
    mma_tf32(acc[1], a, b[0][2], b[0][3]);   // n-octet 1
    mma_tf32(acc[2], a, b[1][0], b[1][1]);   // n-octet 2
    mma_tf32(acc[3], a, b[1][2], b[1][3]);   // n-octet 3
  }

  // ---- epilogue ----
  const float CC = 0.05f, SQC = 0.22360679774997896f, KD = 22.360679774997896f;
  const bool diag = (i0 == j0);
  #pragma unroll
  for (int h = 0; h < 2; ++h) {
    const int rowl = wi * 16 + h * 8 + g4;
    const int ig = i0 + rowl;
    const float n1 = sn1[rowl];
    const float rn1 = srn1[rowl];
    float rs = 0.f;
    #pragma unroll
    for (int oc = 0; oc < 4; ++oc) {
      #pragma unroll
      for (int e = 0; e < 2; ++e) {
        const int col = wj * 32 + oc * 8 + c0 * 2 + e;
        const float g = acc[oc][h * 2 + e];
        const float n2 = sn2[col];
        const float xy = -g;
        const float Af = fmaf(0.1f, xy, fmaf(CC, n2, 1.0f));
        const float Bf = 1.0f - CC * n1;
        const float den = fmaxf(fmaf(0.1f, xy, fmaf(CC * CC, n1 * n2, 1.0f)), 1e-6f);
        const float num2 = Af * Af * n1 + Bf * Bf * n2 + 2.0f * Af * Bf * xy;
        const float s = SQC * sqrtf(fmaxf(num2, 0.0f));
        float r = __fdividef(den + s, fmaxf(den - s, 1e-6f * den));
        r = fminf(r, 2.0e6f);
        const float sim = fmaf(5.0f * g, rn1 * srn2[col], -KD * __logf(r));
        if (diag && rowl == col) g_pos[ig] = sim;
        else rs += __expf(sim);
      }
    }
    rs += __shfl_xor_sync(0xffffffffu, rs, 1);
    rs += __shfl_xor_sync(0xffffffffu, rs, 2);
    if (c0 == 0) rowpart[wj * TT + rowl] = rs;
  }
  __syncthreads();
  if (tid < TT) g_part[(i0 + tid) * NBLK + jb] = rowpart[tid] + rowpart[TT + tid];

  // ---- last-CTA fused final reduction (deterministic order) ----
  __threadfence();
  __syncthreads();
  if (tid == 0) {
    unsigned t = atomicAdd(&g_ctr, 1u);
    *flag = (t == NCTA - 1) ? 1 : 0;
  }
  __syncthreads();
  if (*flag) {
    __threadfence();
    float acc2 = 0.f;
    #pragma unroll
    for (int q = 0; q < 4; ++q) {
      const int i = tid + q * 256;
      const float4* rp = reinterpret_cast<const float4*>(g_part + i * NBLK);
      float4 v0 = rp[0], v1 = rp[1], v2 = rp[2], v3 = rp[3];
      float ssum = (v0.x + v0.y + v0.z + v0.w) + (v1.x + v1.y + v1.z + v1.w) +
                   (v2.x + v2.y + v2.z + v2.w) + (v3.x + v3.y + v3.z + v3.w);
      acc2 += __logf(ssum) - g_pos[i];
    }
    #pragma unroll
    for (int off = 16; off; off >>= 1) acc2 += __shfl_down_sync(0xffffffffu, acc2, off);
    if (lane == 0) red[wid] = acc2;
    __syncthreads();
    if (tid == 0) {
      float tt = 0.f;
      #pragma unroll
      for (int w = 0; w < 8; ++w) tt += red[w];
      out[0] = tt * (1.0f / NB);
      g_ctr = 0;  // reset for next graph replay
    }
  }
}

extern "C" void kernel_launch(void* const* d_in, const int* in_sizes, int n_in,
                              void* d_out, int out_size) {
  const float* z1 = (const float*)d_in[0];
  const float* z2 = (const float*)d_in[1];
  (void)in_sizes; (void)n_in; (void)out_size;

  cudaFuncSetAttribute(hyp_fused, cudaFuncAttributeMaxDynamicSharedMemorySize, SMEM_TOTAL);

  dim3 grid(NBLK, NBLK);
  hyp_fused<<<grid, 256, SMEM_TOTAL>>>(z1, z2, (float*)d_out);
}